// round 1
// baseline (speedup 1.0000x reference)
#include <cuda_runtime.h>
#include <mma.h>
#include <math.h>
#include <stdint.h>

using namespace nvcuda;

// Problem constants
constexpr int BATCH   = 32;
constexpr int HDIM    = 56;
constexpr int C_DIM   = 384;
constexpr int NHEADS  = 12;
constexpr int HEADD   = 32;
constexpr int WS      = 7;
constexpr int SHIFT   = 3;
constexpr int NWIN    = 49;          // WS*WS
constexpr int M_TOK   = BATCH * HDIM * HDIM;   // 100352
constexpr int MLP_HID = 4 * C_DIM;   // 1536

// Scratch buffers (device globals: no allocation allowed)
__device__ float g_ln [(size_t)M_TOK * C_DIM];        // reused for ln1 and ln2
__device__ float g_qkv[(size_t)M_TOK * 3 * C_DIM];
__device__ float g_o  [(size_t)M_TOK * C_DIM];
__device__ float g_h  [(size_t)M_TOK * C_DIM];
__device__ float g_a1 [(size_t)M_TOK * MLP_HID];

// ---------------------------------------------------------------------------
// LayerNorm: one warp per token (C=384 = 96 float4 = 3 float4 per lane)
// ---------------------------------------------------------------------------
__global__ __launch_bounds__(256) void ln_kernel(const float* __restrict__ x,
                                                 const float* __restrict__ g,
                                                 const float* __restrict__ b,
                                                 float* __restrict__ y) {
    int warp = threadIdx.x >> 5, lane = threadIdx.x & 31;
    int m = blockIdx.x * 8 + warp;
    const float4* xr = reinterpret_cast<const float4*>(x + (size_t)m * C_DIM);
    float4 v0 = xr[lane], v1 = xr[lane + 32], v2 = xr[lane + 64];

    float s  = v0.x + v0.y + v0.z + v0.w
             + v1.x + v1.y + v1.z + v1.w
             + v2.x + v2.y + v2.z + v2.w;
    float sq = v0.x*v0.x + v0.y*v0.y + v0.z*v0.z + v0.w*v0.w
             + v1.x*v1.x + v1.y*v1.y + v1.z*v1.z + v1.w*v1.w
             + v2.x*v2.x + v2.y*v2.y + v2.z*v2.z + v2.w*v2.w;
    #pragma unroll
    for (int o = 16; o; o >>= 1) {
        s  += __shfl_xor_sync(0xffffffffu, s,  o);
        sq += __shfl_xor_sync(0xffffffffu, sq, o);
    }
    float mean = s * (1.0f / 384.0f);
    float var  = sq * (1.0f / 384.0f) - mean * mean;
    float rstd = rsqrtf(var + 1e-5f);

    const float4* gr = reinterpret_cast<const float4*>(g);
    const float4* br = reinterpret_cast<const float4*>(b);
    float4* yr = reinterpret_cast<float4*>(y + (size_t)m * C_DIM);
    #pragma unroll
    for (int t = 0; t < 3; t++) {
        int p = lane + 32 * t;
        float4 xv = (t == 0) ? v0 : (t == 1) ? v1 : v2;
        float4 gv = gr[p], bv = br[p], o4;
        o4.x = (xv.x - mean) * rstd * gv.x + bv.x;
        o4.y = (xv.y - mean) * rstd * gv.y + bv.y;
        o4.z = (xv.z - mean) * rstd * gv.z + bv.z;
        o4.w = (xv.w - mean) * rstd * gv.w + bv.w;
        yr[p] = o4;
    }
}

// ---------------------------------------------------------------------------
// TF32 tiled GEMM:  C[M,N] = A[M,K] @ B[K,N] (+bias, +res, gelu variants)
// 128x128x32 block tile, 8 warps (4x2), each warp 32x64 via m16n16k8 wmma.
// EPI: 0 = +bias ; 1 = +bias+res ; 2 = gelu(+bias)
// ---------------------------------------------------------------------------
template <int EPI>
__global__ __launch_bounds__(256) void gemm_tf32(const float* __restrict__ A,
                                                 const float* __restrict__ B,
                                                 const float* __restrict__ bias,
                                                 const float* __restrict__ R,
                                                 float* __restrict__ C,
                                                 int M, int N, int K) {
    __shared__ float As[128][36];   // [m][k], padded
    __shared__ float Bs[32][132];   // [k][n], padded
    __shared__ float Cbuf[8][256];  // per-warp 16x16 staging

    int tid = threadIdx.x;
    int warp = tid >> 5, lane = tid & 31;
    int wm = warp >> 1, wn = warp & 1;          // 4 x 2 warp grid
    int m0 = blockIdx.y * 128, n0 = blockIdx.x * 128;

    wmma::fragment<wmma::accumulator, 16, 16, 8, float> acc[2][4];
    #pragma unroll
    for (int i = 0; i < 2; i++)
        #pragma unroll
        for (int j = 0; j < 4; j++)
            wmma::fill_fragment(acc[i][j], 0.0f);

    for (int k0 = 0; k0 < K; k0 += 32) {
        // load A tile: 128x32 floats = 1024 float4
        #pragma unroll
        for (int t = 0; t < 4; t++) {
            int f = tid + t * 256;
            int row = f >> 3, kq = (f & 7) << 2;
            float4 v = *reinterpret_cast<const float4*>(
                A + (size_t)(m0 + row) * K + k0 + kq);
            *reinterpret_cast<float4*>(&As[row][kq]) = v;
        }
        // load B tile: 32x128 floats = 1024 float4
        #pragma unroll
        for (int t = 0; t < 4; t++) {
            int f = tid + t * 256;
            int row = f >> 5, nq = (f & 31) << 2;
            float4 v = *reinterpret_cast<const float4*>(
                B + (size_t)(k0 + row) * N + n0 + nq);
            *reinterpret_cast<float4*>(&Bs[row][nq]) = v;
        }
        __syncthreads();

        #pragma unroll
        for (int kk = 0; kk < 4; kk++) {
            wmma::fragment<wmma::matrix_a, 16, 16, 8, wmma::precision::tf32,
                           wmma::row_major> af[2];
            wmma::fragment<wmma::matrix_b, 16, 16, 8, wmma::precision::tf32,
                           wmma::row_major> bf[4];
            #pragma unroll
            for (int i = 0; i < 2; i++) {
                wmma::load_matrix_sync(af[i], &As[wm * 32 + i * 16][kk * 8], 36);
                #pragma unroll
                for (int e = 0; e < af[i].num_elements; e++)
                    af[i].x[e] = wmma::__float_to_tf32(af[i].x[e]);
            }
            #pragma unroll
            for (int j = 0; j < 4; j++) {
                wmma::load_matrix_sync(bf[j], &Bs[kk * 8][wn * 64 + j * 16], 132);
                #pragma unroll
                for (int e = 0; e < bf[j].num_elements; e++)
                    bf[j].x[e] = wmma::__float_to_tf32(bf[j].x[e]);
            }
            #pragma unroll
            for (int i = 0; i < 2; i++)
                #pragma unroll
                for (int j = 0; j < 4; j++)
                    wmma::mma_sync(acc[i][j], af[i], bf[j], acc[i][j]);
        }
        __syncthreads();
    }

    // epilogue: each lane handles 8 contiguous floats of a 16x16 tile
    int erow = lane >> 1;
    int ecol = (lane & 1) << 3;
    #pragma unroll
    for (int i = 0; i < 2; i++) {
        #pragma unroll
        for (int j = 0; j < 4; j++) {
            __syncwarp();
            wmma::store_matrix_sync(&Cbuf[warp][0], acc[i][j], 16, wmma::mem_row_major);
            __syncwarp();
            int gm  = m0 + wm * 32 + i * 16 + erow;
            int gn  = n0 + wn * 64 + j * 16 + ecol;
            float*       dst = C + (size_t)gm * N + gn;
            const float* src = &Cbuf[warp][erow * 16 + ecol];
            const float* rr  = (EPI == 1) ? (R + (size_t)gm * N + gn) : nullptr;
            #pragma unroll
            for (int u = 0; u < 8; u++) {
                float v = src[u] + bias[gn + u];
                if (EPI == 1) v += rr[u];
                if (EPI == 2) v = 0.5f * v * (1.0f + erff(v * 0.70710678118654752f));
                dst[u] = v;
            }
        }
    }
}

// ---------------------------------------------------------------------------
// Windowed shifted attention: one block per (head, window).
// Shift/roll + window partition/reverse folded into the token index mapping.
// ---------------------------------------------------------------------------
__global__ __launch_bounds__(256) void attn_kernel(const float* __restrict__ qkv,
                                                   const float* __restrict__ table,
                                                   const int* __restrict__ relidx,
                                                   float* __restrict__ o) {
    __shared__ float qs[NWIN][33], ks[NWIN][33], vs[NWIN][33];
    __shared__ float ss[NWIN][50];
    __shared__ int   sidx[NWIN];

    int head = blockIdx.x;
    int w    = blockIdx.y;
    int tid  = threadIdx.x, warp = tid >> 5, lane = tid & 31;

    int b  = w >> 6;
    int wr = w & 63;
    int wi = wr >> 3, wj = wr & 7;

    if (tid < NWIN) {
        int i = tid / 7, j = tid - 7 * (tid / 7);
        int rr = wi * 7 + i + SHIFT; if (rr >= HDIM) rr -= HDIM;
        int cc = wj * 7 + j + SHIFT; if (cc >= HDIM) cc -= HDIM;
        sidx[tid] = b * (HDIM * HDIM) + rr * HDIM + cc;
    }
    __syncthreads();

    // gather q,k,v rows (32 floats each, one lane each)
    for (int r = warp; r < NWIN; r += 8) {
        const float* base = qkv + (size_t)sidx[r] * (3 * C_DIM) + head * HEADD;
        qs[r][lane] = base[lane];
        ks[r][lane] = base[C_DIM + lane];
        vs[r][lane] = base[2 * C_DIM + lane];
    }
    __syncthreads();

    const float scale = 0.17677669529663687f;  // 1/sqrt(32)
    for (int e = tid; e < NWIN * NWIN; e += 256) {
        int i = e / NWIN, j = e - i * NWIN;
        float s = 0.0f;
        #pragma unroll
        for (int d = 0; d < HEADD; d++) s += qs[i][d] * ks[j][d];
        s = s * scale + table[relidx[e] * NHEADS + head];
        ss[i][j] = s;
    }
    __syncthreads();

    // row softmax (warp per row)
    for (int i = warp; i < NWIN; i += 8) {
        float mx = -1e30f;
        for (int j = lane; j < NWIN; j += 32) mx = fmaxf(mx, ss[i][j]);
        #pragma unroll
        for (int off = 16; off; off >>= 1)
            mx = fmaxf(mx, __shfl_xor_sync(0xffffffffu, mx, off));
        float sum = 0.0f;
        for (int j = lane; j < NWIN; j += 32) {
            float p = __expf(ss[i][j] - mx);
            ss[i][j] = p;
            sum += p;
        }
        #pragma unroll
        for (int off = 16; off; off >>= 1)
            sum += __shfl_xor_sync(0xffffffffu, sum, off);
        float inv = 1.0f / sum;
        for (int j = lane; j < NWIN; j += 32) ss[i][j] *= inv;
    }
    __syncthreads();

    // O = P @ V, scatter back through the same (shifted) index map
    for (int e = tid; e < NWIN * HEADD; e += 256) {
        int i = e >> 5, d = e & 31;
        float s = 0.0f;
        #pragma unroll
        for (int j = 0; j < NWIN; j++) s += ss[i][j] * vs[j][d];
        o[(size_t)sidx[i] * C_DIM + head * HEADD + d] = s;
    }
}

// ---------------------------------------------------------------------------
extern "C" void kernel_launch(void* const* d_in, const int* in_sizes, int n_in,
                              void* d_out, int out_size) {
    const float* x      = (const float*)d_in[0];
    const float* n1g    = (const float*)d_in[1];
    const float* n1b    = (const float*)d_in[2];
    const float* qkvw   = (const float*)d_in[3];
    const float* qkvb   = (const float*)d_in[4];
    const float* projw  = (const float*)d_in[5];
    const float* projb  = (const float*)d_in[6];
    const float* table  = (const float*)d_in[7];
    const float* n2g    = (const float*)d_in[8];
    const float* n2b    = (const float*)d_in[9];
    const float* fc1w   = (const float*)d_in[10];
    const float* fc1b   = (const float*)d_in[11];
    const float* fc2w   = (const float*)d_in[12];
    const float* fc2b   = (const float*)d_in[13];
    const int*   relidx = (const int*)d_in[14];
    float* out = (float*)d_out;

    float *ln, *qkv, *o, *h, *a1;
    cudaGetSymbolAddress((void**)&ln,  g_ln);
    cudaGetSymbolAddress((void**)&qkv, g_qkv);
    cudaGetSymbolAddress((void**)&o,   g_o);
    cudaGetSymbolAddress((void**)&h,   g_h);
    cudaGetSymbolAddress((void**)&a1,  g_a1);

    // 1) LN1
    ln_kernel<<<M_TOK / 8, 256>>>(x, n1g, n1b, ln);
    // 2) QKV = ln1 @ qkv_w + b
    gemm_tf32<0><<<dim3(3 * C_DIM / 128, M_TOK / 128), 256>>>(
        ln, qkvw, qkvb, nullptr, qkv, M_TOK, 3 * C_DIM, C_DIM);
    // 3) windowed attention (shift folded into indices)
    attn_kernel<<<dim3(NHEADS, 2048), 256>>>(qkv, table, relidx, o);
    // 4) h = x + (o @ proj_w + b)
    gemm_tf32<1><<<dim3(C_DIM / 128, M_TOK / 128), 256>>>(
        o, projw, projb, x, h, M_TOK, C_DIM, C_DIM);
    // 5) LN2
    ln_kernel<<<M_TOK / 8, 256>>>(h, n2g, n2b, ln);
    // 6) a1 = gelu(ln2 @ fc1_w + b)
    gemm_tf32<2><<<dim3(MLP_HID / 128, M_TOK / 128), 256>>>(
        ln, fc1w, fc1b, nullptr, a1, M_TOK, MLP_HID, C_DIM);
    // 7) out = h + (a1 @ fc2_w + b)
    gemm_tf32<1><<<dim3(C_DIM / 128, M_TOK / 128), 256>>>(
        a1, fc2w, fc2b, h, out, M_TOK, C_DIM, MLP_HID);
}

// round 3
// speedup vs baseline: 3.7804x; 3.7804x over previous
#include <cuda_runtime.h>
#include <cuda_fp16.h>
#include <math.h>
#include <stdint.h>

// Problem constants
constexpr int BATCH   = 32;
constexpr int HDIM    = 56;
constexpr int C_DIM   = 384;
constexpr int NHEADS  = 12;
constexpr int HEADD   = 32;
constexpr int WS      = 7;
constexpr int SHIFT   = 3;
constexpr int NWIN    = 49;
constexpr int M_TOK   = BATCH * HDIM * HDIM;   // 100352
constexpr int MLP_HID = 4 * C_DIM;             // 1536

constexpr int NSTAGE     = 4;
constexpr int STAGE_B    = 16384;              // A 8KB + B 8KB (fp16)
constexpr int SMEM_BYTES = NSTAGE * STAGE_B;   // 64KB

// Scratch buffers (device globals: no allocation allowed)
__device__ __align__(256) __half g_ln [(size_t)M_TOK * C_DIM];
__device__ __align__(256) __half g_qkv[(size_t)M_TOK * 3 * C_DIM];
__device__ __align__(256) __half g_o  [(size_t)M_TOK * C_DIM];
__device__ __align__(256) float  g_h  [(size_t)M_TOK * C_DIM];
__device__ __align__(256) __half g_a1 [(size_t)M_TOK * MLP_HID];
// fp16 transposed weights [N][K]
__device__ __align__(256) __half g_bt_qkv [(size_t)3 * C_DIM * C_DIM];
__device__ __align__(256) __half g_bt_proj[(size_t)C_DIM * C_DIM];
__device__ __align__(256) __half g_bt_fc1 [(size_t)MLP_HID * C_DIM];
__device__ __align__(256) __half g_bt_fc2 [(size_t)C_DIM * MLP_HID];

// ---------------------------------------------------------------------------
// asm helpers (all base-arch: cp.async sm80, ldmatrix sm75, mma.sync sm80)
// ---------------------------------------------------------------------------
__device__ __forceinline__ uint32_t smem_u32(const void* p) {
    uint32_t a;
    asm("{ .reg .u64 t; cvta.to.shared.u64 t, %1; cvt.u32.u64 %0, t; }"
        : "=r"(a) : "l"(p));
    return a;
}
__device__ __forceinline__ void cp16(uint32_t dst, const void* src) {
    asm volatile("cp.async.cg.shared.global [%0], [%1], 16;"
                 :: "r"(dst), "l"(src) : "memory");
}
__device__ __forceinline__ void cp_commit() {
    asm volatile("cp.async.commit_group;" ::: "memory");
}
template <int N>
__device__ __forceinline__ void cp_wait() {
    asm volatile("cp.async.wait_group %0;" :: "n"(N) : "memory");
}
__device__ __forceinline__ void ldmx4(uint32_t& r0, uint32_t& r1,
                                      uint32_t& r2, uint32_t& r3, uint32_t addr) {
    asm volatile("ldmatrix.sync.aligned.m8n8.x4.shared.b16 {%0,%1,%2,%3}, [%4];"
                 : "=r"(r0), "=r"(r1), "=r"(r2), "=r"(r3) : "r"(addr));
}
__device__ __forceinline__ void mma16816(float* c, const uint32_t* a,
                                         const uint32_t* b) {
    asm volatile(
        "mma.sync.aligned.m16n8k16.row.col.f32.f16.f16.f32 "
        "{%0,%1,%2,%3}, {%4,%5,%6,%7}, {%8,%9}, {%0,%1,%2,%3};"
        : "+f"(c[0]), "+f"(c[1]), "+f"(c[2]), "+f"(c[3])
        : "r"(a[0]), "r"(a[1]), "r"(a[2]), "r"(a[3]), "r"(b[0]), "r"(b[1]));
}
// smem tile layout: [128 rows][32 fp16] = 64B rows; 16B chunk c4 swizzled by row
__device__ __forceinline__ uint32_t sa_off(int row, int c4) {
    return (uint32_t)(row * 64 + ((c4 ^ ((row >> 1) & 3)) << 4));
}
__device__ __forceinline__ float gelu(float v) {
    return 0.5f * v * (1.0f + erff(v * 0.70710678118654752f));
}

// ---------------------------------------------------------------------------
// Weight prep: W[K][N] fp32 -> Wt[N][K] fp16
// ---------------------------------------------------------------------------
__global__ __launch_bounds__(256) void prep_w(const float* __restrict__ W,
                                              __half* __restrict__ Wt,
                                              int K, int N) {
    int idx = blockIdx.x * 256 + threadIdx.x;
    if (idx >= K * N) return;
    int k = idx / N, n = idx - k * N;
    Wt[(size_t)n * K + k] = __float2half_rn(W[idx]);
}

// ---------------------------------------------------------------------------
// fp16 HMMA GEMM: C[M,N] = A[M,K] @ Bt[N,K]^T  (+bias / +res / gelu)
// 128x128 CTA tile, 256 thr, 8 warps (4x2 -> 32x64 warp tile), 4-stage cp.async.
// EPI: 0 = +bias -> half ; 1 = +bias+res -> float ; 2 = gelu(+bias) -> half
// ---------------------------------------------------------------------------
template <int EPI>
__global__ __launch_bounds__(256, 2)
void gemm_hmma(const __half* __restrict__ A, const __half* __restrict__ Bt,
               const float* __restrict__ bias, const float* __restrict__ R,
               void* __restrict__ out, int M, int N, int K) {
    extern __shared__ __align__(128) char smem[];
    uint32_t sbase = smem_u32(smem);

    int tid = threadIdx.x, warp = tid >> 5, lane = tid & 31;
    int wm = warp >> 1, wn = warp & 1;
    int m0 = blockIdx.y * 128, n0 = blockIdx.x * 128;
    int NC = K >> 5;

    float acc[2][8][4];
    #pragma unroll
    for (int i = 0; i < 2; i++)
        #pragma unroll
        for (int j = 0; j < 8; j++)
            #pragma unroll
            for (int e = 0; e < 4; e++) acc[i][j][e] = 0.0f;

    auto load_chunk = [&](int kc, int s) {
        uint32_t ast = sbase + s * STAGE_B;
        uint32_t bst = ast + 8192;
        #pragma unroll
        for (int t = 0; t < 2; t++) {
            int seg = tid + t * 256;
            int row = seg >> 2, q = seg & 3;
            cp16(ast + sa_off(row, q),
                 A + (size_t)(m0 + row) * K + kc * 32 + q * 8);
            cp16(bst + sa_off(row, q),
                 Bt + (size_t)(n0 + row) * K + kc * 32 + q * 8);
        }
    };

    // prologue: stages 0..2
    #pragma unroll
    for (int c = 0; c < NSTAGE - 1; c++) { load_chunk(c, c); cp_commit(); }

    for (int c = 0; c < NC; c++) {
        cp_wait<NSTAGE - 2>();
        __syncthreads();
        int cn = c + NSTAGE - 1;
        if (cn < NC) load_chunk(cn, cn & (NSTAGE - 1));
        cp_commit();

        uint32_t ast = sbase + (c & (NSTAGE - 1)) * STAGE_B;
        uint32_t bst = ast + 8192;
        #pragma unroll
        for (int kk = 0; kk < 2; kk++) {
            uint32_t a[2][4], b[4][4];
            #pragma unroll
            for (int i = 0; i < 2; i++) {
                int row = wm * 32 + i * 16 + (lane & 15);
                int c4  = kk * 2 + (lane >> 4);
                ldmx4(a[i][0], a[i][1], a[i][2], a[i][3], ast + sa_off(row, c4));
            }
            #pragma unroll
            for (int jp = 0; jp < 4; jp++) {
                int row = wn * 64 + jp * 16 + (lane & 7) + ((lane >> 4) << 3);
                int c4  = kk * 2 + ((lane >> 3) & 1);
                ldmx4(b[jp][0], b[jp][1], b[jp][2], b[jp][3], bst + sa_off(row, c4));
            }
            #pragma unroll
            for (int i = 0; i < 2; i++)
                #pragma unroll
                for (int jp = 0; jp < 4; jp++) {
                    mma16816(acc[i][jp * 2 + 0], a[i], &b[jp][0]);
                    mma16816(acc[i][jp * 2 + 1], a[i], &b[jp][2]);
                }
        }
    }

    // register epilogue
    int rbase = m0 + wm * 32 + (lane >> 2);
    #pragma unroll
    for (int i = 0; i < 2; i++) {
        #pragma unroll
        for (int j = 0; j < 8; j++) {
            int col = n0 + wn * 64 + j * 8 + ((lane & 3) << 1);
            float b0 = bias[col], b1 = bias[col + 1];
            #pragma unroll
            for (int half_m = 0; half_m < 2; half_m++) {
                int row = rbase + i * 16 + half_m * 8;
                float v0 = acc[i][j][half_m * 2 + 0] + b0;
                float v1 = acc[i][j][half_m * 2 + 1] + b1;
                if (EPI == 1) {
                    const float2 r2 = *reinterpret_cast<const float2*>(
                        R + (size_t)row * N + col);
                    v0 += r2.x; v1 += r2.y;
                    *reinterpret_cast<float2*>((float*)out + (size_t)row * N + col)
                        = make_float2(v0, v1);
                } else {
                    if (EPI == 2) { v0 = gelu(v0); v1 = gelu(v1); }
                    *reinterpret_cast<__half2*>((__half*)out + (size_t)row * N + col)
                        = __floats2half2_rn(v0, v1);
                }
            }
        }
    }
}

// ---------------------------------------------------------------------------
// LayerNorm: one warp per token, fp32 in -> fp16 out
// ---------------------------------------------------------------------------
__global__ __launch_bounds__(256) void ln_kernel(const float* __restrict__ x,
                                                 const float* __restrict__ g,
                                                 const float* __restrict__ b,
                                                 __half* __restrict__ y) {
    int warp = threadIdx.x >> 5, lane = threadIdx.x & 31;
    int m = blockIdx.x * 8 + warp;
    const float4* xr = reinterpret_cast<const float4*>(x + (size_t)m * C_DIM);
    float4 v0 = xr[lane], v1 = xr[lane + 32], v2 = xr[lane + 64];

    float s  = v0.x + v0.y + v0.z + v0.w + v1.x + v1.y + v1.z + v1.w
             + v2.x + v2.y + v2.z + v2.w;
    float sq = v0.x*v0.x + v0.y*v0.y + v0.z*v0.z + v0.w*v0.w
             + v1.x*v1.x + v1.y*v1.y + v1.z*v1.z + v1.w*v1.w
             + v2.x*v2.x + v2.y*v2.y + v2.z*v2.z + v2.w*v2.w;
    #pragma unroll
    for (int o = 16; o; o >>= 1) {
        s  += __shfl_xor_sync(0xffffffffu, s,  o);
        sq += __shfl_xor_sync(0xffffffffu, sq, o);
    }
    float mean = s * (1.0f / 384.0f);
    float var  = sq * (1.0f / 384.0f) - mean * mean;
    float rstd = rsqrtf(var + 1e-5f);

    const float4* gr = reinterpret_cast<const float4*>(g);
    const float4* br = reinterpret_cast<const float4*>(b);
    __half2* yr = reinterpret_cast<__half2*>(y + (size_t)m * C_DIM);
    #pragma unroll
    for (int t = 0; t < 3; t++) {
        int p = lane + 32 * t;
        float4 xv = (t == 0) ? v0 : (t == 1) ? v1 : v2;
        float4 gv = gr[p], bv = br[p];
        yr[p * 2 + 0] = __floats2half2_rn((xv.x - mean) * rstd * gv.x + bv.x,
                                          (xv.y - mean) * rstd * gv.y + bv.y);
        yr[p * 2 + 1] = __floats2half2_rn((xv.z - mean) * rstd * gv.z + bv.z,
                                          (xv.w - mean) * rstd * gv.w + bv.w);
    }
}

// ---------------------------------------------------------------------------
// Windowed shifted attention: one block per (head, window); fp16 I/O
// ---------------------------------------------------------------------------
__global__ __launch_bounds__(256) void attn_kernel(const __half* __restrict__ qkv,
                                                   const float* __restrict__ table,
                                                   const int* __restrict__ relidx,
                                                   __half* __restrict__ o) {
    __shared__ float qs[NWIN][33], ks[NWIN][33], vs[NWIN][33];
    __shared__ float ss[NWIN][50];
    __shared__ int   sidx[NWIN];

    int head = blockIdx.x;
    int w    = blockIdx.y;
    int tid  = threadIdx.x, warp = tid >> 5, lane = tid & 31;

    int b  = w >> 6;
    int wr = w & 63;
    int wi = wr >> 3, wj = wr & 7;

    if (tid < NWIN) {
        int i = tid / 7, j = tid - 7 * (tid / 7);
        int rr = wi * 7 + i + SHIFT; if (rr >= HDIM) rr -= HDIM;
        int cc = wj * 7 + j + SHIFT; if (cc >= HDIM) cc -= HDIM;
        sidx[tid] = b * (HDIM * HDIM) + rr * HDIM + cc;
    }
    __syncthreads();

    for (int r = warp; r < NWIN; r += 8) {
        const __half* base = qkv + (size_t)sidx[r] * (3 * C_DIM) + head * HEADD;
        qs[r][lane] = __half2float(base[lane]);
        ks[r][lane] = __half2float(base[C_DIM + lane]);
        vs[r][lane] = __half2float(base[2 * C_DIM + lane]);
    }
    __syncthreads();

    const float scale = 0.17677669529663687f;
    for (int e = tid; e < NWIN * NWIN; e += 256) {
        int i = e / NWIN, j = e - i * NWIN;
        float s = 0.0f;
        #pragma unroll
        for (int d = 0; d < HEADD; d++) s += qs[i][d] * ks[j][d];
        ss[i][j] = s * scale + table[relidx[e] * NHEADS + head];
    }
    __syncthreads();

    for (int i = warp; i < NWIN; i += 8) {
        float mx = -1e30f;
        for (int j = lane; j < NWIN; j += 32) mx = fmaxf(mx, ss[i][j]);
        #pragma unroll
        for (int off = 16; off; off >>= 1)
            mx = fmaxf(mx, __shfl_xor_sync(0xffffffffu, mx, off));
        float sum = 0.0f;
        for (int j = lane; j < NWIN; j += 32) {
            float p = __expf(ss[i][j] - mx);
            ss[i][j] = p;
            sum += p;
        }
        #pragma unroll
        for (int off = 16; off; off >>= 1)
            sum += __shfl_xor_sync(0xffffffffu, sum, off);
        float inv = 1.0f / sum;
        for (int j = lane; j < NWIN; j += 32) ss[i][j] *= inv;
    }
    __syncthreads();

    for (int e = tid; e < NWIN * HEADD; e += 256) {
        int i = e >> 5, d = e & 31;
        float s = 0.0f;
        #pragma unroll
        for (int j = 0; j < NWIN; j++) s += ss[i][j] * vs[j][d];
        o[(size_t)sidx[i] * C_DIM + head * HEADD + d] = __float2half_rn(s);
    }
}

// ---------------------------------------------------------------------------
extern "C" void kernel_launch(void* const* d_in, const int* in_sizes, int n_in,
                              void* d_out, int out_size) {
    const float* x      = (const float*)d_in[0];
    const float* n1g    = (const float*)d_in[1];
    const float* n1b    = (const float*)d_in[2];
    const float* qkvw   = (const float*)d_in[3];
    const float* qkvb   = (const float*)d_in[4];
    const float* projw  = (const float*)d_in[5];
    const float* projb  = (const float*)d_in[6];
    const float* table  = (const float*)d_in[7];
    const float* n2g    = (const float*)d_in[8];
    const float* n2b    = (const float*)d_in[9];
    const float* fc1w   = (const float*)d_in[10];
    const float* fc1b   = (const float*)d_in[11];
    const float* fc2w   = (const float*)d_in[12];
    const float* fc2b   = (const float*)d_in[13];
    const int*   relidx = (const int*)d_in[14];
    float* out = (float*)d_out;

    __half *ln, *qkv, *o, *a1, *btq, *btp, *bt1, *bt2;
    float *h;
    cudaGetSymbolAddress((void**)&ln,  g_ln);
    cudaGetSymbolAddress((void**)&qkv, g_qkv);
    cudaGetSymbolAddress((void**)&o,   g_o);
    cudaGetSymbolAddress((void**)&h,   g_h);
    cudaGetSymbolAddress((void**)&a1,  g_a1);
    cudaGetSymbolAddress((void**)&btq, g_bt_qkv);
    cudaGetSymbolAddress((void**)&btp, g_bt_proj);
    cudaGetSymbolAddress((void**)&bt1, g_bt_fc1);
    cudaGetSymbolAddress((void**)&bt2, g_bt_fc2);

    cudaFuncSetAttribute(gemm_hmma<0>, cudaFuncAttributeMaxDynamicSharedMemorySize, SMEM_BYTES);
    cudaFuncSetAttribute(gemm_hmma<1>, cudaFuncAttributeMaxDynamicSharedMemorySize, SMEM_BYTES);
    cudaFuncSetAttribute(gemm_hmma<2>, cudaFuncAttributeMaxDynamicSharedMemorySize, SMEM_BYTES);

    // weight prep (fp32 [K][N] -> fp16 [N][K])
    prep_w<<<(C_DIM * 3 * C_DIM) / 256, 256>>>(qkvw, btq, C_DIM, 3 * C_DIM);
    prep_w<<<(C_DIM * C_DIM) / 256,     256>>>(projw, btp, C_DIM, C_DIM);
    prep_w<<<(C_DIM * MLP_HID) / 256,   256>>>(fc1w, bt1, C_DIM, MLP_HID);
    prep_w<<<(MLP_HID * C_DIM) / 256,   256>>>(fc2w, bt2, MLP_HID, C_DIM);

    // 1) LN1: x -> ln (fp16)
    ln_kernel<<<M_TOK / 8, 256>>>(x, n1g, n1b, ln);
    // 2) qkv = ln @ qkv_w + b   (fp16 out)
    gemm_hmma<0><<<dim3(3 * C_DIM / 128, M_TOK / 128), 256, SMEM_BYTES>>>(
        ln, btq, qkvb, nullptr, qkv, M_TOK, 3 * C_DIM, C_DIM);
    // 3) windowed attention (shift folded into indices), fp16 out
    attn_kernel<<<dim3(NHEADS, 2048), 256>>>(qkv, table, relidx, o);
    // 4) h = x + proj(o)   (fp32 out)
    gemm_hmma<1><<<dim3(C_DIM / 128, M_TOK / 128), 256, SMEM_BYTES>>>(
        o, btp, projb, x, h, M_TOK, C_DIM, C_DIM);
    // 5) LN2: h -> ln (fp16)
    ln_kernel<<<M_TOK / 8, 256>>>(h, n2g, n2b, ln);
    // 6) a1 = gelu(fc1(ln))  (fp16 out)
    gemm_hmma<2><<<dim3(MLP_HID / 128, M_TOK / 128), 256, SMEM_BYTES>>>(
        ln, bt1, fc1b, nullptr, a1, M_TOK, MLP_HID, C_DIM);
    // 7) out = h + fc2(a1)   (fp32 out)
    gemm_hmma<1><<<dim3(C_DIM / 128, M_TOK / 128), 256, SMEM_BYTES>>>(
        a1, bt2, fc2b, h, out, M_TOK, C_DIM, MLP_HID);
}

// round 4
// speedup vs baseline: 4.3170x; 1.1419x over previous
#include <cuda_runtime.h>
#include <cuda_fp16.h>
#include <math.h>
#include <stdint.h>

// Problem constants
constexpr int BATCH   = 32;
constexpr int HDIM    = 56;
constexpr int C_DIM   = 384;
constexpr int NHEADS  = 12;
constexpr int HEADD   = 32;
constexpr int WS      = 7;
constexpr int SHIFT   = 3;
constexpr int NWIN    = 49;
constexpr int M_TOK   = BATCH * HDIM * HDIM;   // 100352
constexpr int MLP_HID = 4 * C_DIM;             // 1536

constexpr int NSTAGE     = 3;
constexpr int STAGE_B    = 32768;              // A 16KB + B 16KB (fp16, k64)
constexpr int SMEM_BYTES = NSTAGE * STAGE_B;   // 96KB

// Scratch buffers (device globals: no allocation allowed)
__device__ __align__(256) __half g_ln [(size_t)M_TOK * C_DIM];
__device__ __align__(256) __half g_qkv[(size_t)M_TOK * 3 * C_DIM];
__device__ __align__(256) __half g_o  [(size_t)M_TOK * C_DIM];
__device__ __align__(256) float  g_h  [(size_t)M_TOK * C_DIM];
__device__ __align__(256) __half g_a1 [(size_t)M_TOK * MLP_HID];
// fp16 transposed weights [N][K]
__device__ __align__(256) __half g_bt_qkv [(size_t)3 * C_DIM * C_DIM];
__device__ __align__(256) __half g_bt_proj[(size_t)C_DIM * C_DIM];
__device__ __align__(256) __half g_bt_fc1 [(size_t)MLP_HID * C_DIM];
__device__ __align__(256) __half g_bt_fc2 [(size_t)C_DIM * MLP_HID];

// ---------------------------------------------------------------------------
// asm helpers (base-arch only: cp.async sm80, ldmatrix sm75, mma.sync sm80)
// ---------------------------------------------------------------------------
__device__ __forceinline__ uint32_t smem_u32(const void* p) {
    uint32_t a;
    asm("{ .reg .u64 t; cvta.to.shared.u64 t, %1; cvt.u32.u64 %0, t; }"
        : "=r"(a) : "l"(p));
    return a;
}
__device__ __forceinline__ void cp16(uint32_t dst, const void* src) {
    asm volatile("cp.async.cg.shared.global [%0], [%1], 16;"
                 :: "r"(dst), "l"(src) : "memory");
}
__device__ __forceinline__ void cp_commit() {
    asm volatile("cp.async.commit_group;" ::: "memory");
}
template <int N>
__device__ __forceinline__ void cp_wait() {
    asm volatile("cp.async.wait_group %0;" :: "n"(N) : "memory");
}
__device__ __forceinline__ void ldmx4(uint32_t& r0, uint32_t& r1,
                                      uint32_t& r2, uint32_t& r3, uint32_t addr) {
    asm volatile("ldmatrix.sync.aligned.m8n8.x4.shared.b16 {%0,%1,%2,%3}, [%4];"
                 : "=r"(r0), "=r"(r1), "=r"(r2), "=r"(r3) : "r"(addr));
}
__device__ __forceinline__ void mma16816(float* c, const uint32_t* a,
                                         const uint32_t* b) {
    asm volatile(
        "mma.sync.aligned.m16n8k16.row.col.f32.f16.f16.f32 "
        "{%0,%1,%2,%3}, {%4,%5,%6,%7}, {%8,%9}, {%0,%1,%2,%3};"
        : "+f"(c[0]), "+f"(c[1]), "+f"(c[2]), "+f"(c[3])
        : "r"(a[0]), "r"(a[1]), "r"(a[2]), "r"(a[3]), "r"(b[0]), "r"(b[1]));
}
// smem tile: [128 rows][64 fp16] = 128B rows (8x16B chunks), XOR-8 swizzle
__device__ __forceinline__ uint32_t sa_off(int row, int c4) {
    return (uint32_t)(row * 128 + ((c4 ^ (row & 7)) << 4));
}
__device__ __forceinline__ float gelu(float v) {
    return 0.5f * v * (1.0f + erff(v * 0.70710678118654752f));
}

// ---------------------------------------------------------------------------
// Weight prep: W[K][N] fp32 -> Wt[N][K] fp16
// ---------------------------------------------------------------------------
__global__ __launch_bounds__(256) void prep_w(const float* __restrict__ W,
                                              __half* __restrict__ Wt,
                                              int K, int N) {
    int idx = blockIdx.x * 256 + threadIdx.x;
    if (idx >= K * N) return;
    int k = idx / N, n = idx - k * N;
    Wt[(size_t)n * K + k] = __float2half_rn(W[idx]);
}

// ---------------------------------------------------------------------------
// fp16 HMMA GEMM: C[M,N] = A[M,K] @ Bt[N,K]^T  (+bias / +res / gelu)
// 128x128 CTA tile, 256 thr, 8 warps (4x2 -> 32x64 warp tile),
// K-chunk 64, 3-stage cp.async pipeline.
// EPI: 0 = +bias -> half ; 1 = +bias+res -> float ; 2 = gelu(+bias) -> half
// ---------------------------------------------------------------------------
template <int EPI>
__global__ __launch_bounds__(256, 2)
void gemm_hmma(const __half* __restrict__ A, const __half* __restrict__ Bt,
               const float* __restrict__ bias, const float* __restrict__ R,
               void* __restrict__ out, int M, int N, int K) {
    extern __shared__ __align__(128) char smem[];
    uint32_t sbase = smem_u32(smem);

    int tid = threadIdx.x, warp = tid >> 5, lane = tid & 31;
    int wm = warp >> 1, wn = warp & 1;
    int m0 = blockIdx.y * 128, n0 = blockIdx.x * 128;
    int NC = K >> 6;   // k64 chunks

    float acc[2][8][4];
    #pragma unroll
    for (int i = 0; i < 2; i++)
        #pragma unroll
        for (int j = 0; j < 8; j++)
            #pragma unroll
            for (int e = 0; e < 4; e++) acc[i][j][e] = 0.0f;

    auto load_chunk = [&](int kc, int s) {
        uint32_t ast = sbase + s * STAGE_B;
        uint32_t bst = ast + 16384;
        #pragma unroll
        for (int t = 0; t < 4; t++) {
            int seg = tid + t * 256;
            int row = seg >> 3, q = seg & 7;          // 8 chunks per 128B row
            cp16(ast + sa_off(row, q),
                 A + (size_t)(m0 + row) * K + kc * 64 + q * 8);
            cp16(bst + sa_off(row, q),
                 Bt + (size_t)(n0 + row) * K + kc * 64 + q * 8);
        }
    };

    // prologue: 2 stages in flight
    #pragma unroll
    for (int c = 0; c < NSTAGE - 1; c++) { load_chunk(c, c); cp_commit(); }

    int s_cur = 0, s_nxt = NSTAGE - 1;
    for (int c = 0; c < NC; c++) {
        cp_wait<NSTAGE - 2>();
        __syncthreads();
        int cn = c + NSTAGE - 1;
        if (cn < NC) load_chunk(cn, s_nxt);
        cp_commit();
        if (++s_nxt == NSTAGE) s_nxt = 0;

        uint32_t ast = sbase + s_cur * STAGE_B;
        uint32_t bst = ast + 16384;
        if (++s_cur == NSTAGE) s_cur = 0;

        #pragma unroll
        for (int kk = 0; kk < 4; kk++) {
            uint32_t a[2][4], b[4][4];
            #pragma unroll
            for (int i = 0; i < 2; i++) {
                int row = wm * 32 + i * 16 + (lane & 15);
                int c4  = kk * 2 + (lane >> 4);
                ldmx4(a[i][0], a[i][1], a[i][2], a[i][3], ast + sa_off(row, c4));
            }
            #pragma unroll
            for (int jp = 0; jp < 4; jp++) {
                int row = wn * 64 + jp * 16 + (lane & 7) + ((lane >> 4) << 3);
                int c4  = kk * 2 + ((lane >> 3) & 1);
                ldmx4(b[jp][0], b[jp][1], b[jp][2], b[jp][3], bst + sa_off(row, c4));
            }
            #pragma unroll
            for (int i = 0; i < 2; i++)
                #pragma unroll
                for (int jp = 0; jp < 4; jp++) {
                    mma16816(acc[i][jp * 2 + 0], a[i], &b[jp][0]);
                    mma16816(acc[i][jp * 2 + 1], a[i], &b[jp][2]);
                }
        }
    }

    // register epilogue
    int rbase = m0 + wm * 32 + (lane >> 2);
    #pragma unroll
    for (int i = 0; i < 2; i++) {
        #pragma unroll
        for (int j = 0; j < 8; j++) {
            int col = n0 + wn * 64 + j * 8 + ((lane & 3) << 1);
            float b0 = bias[col], b1 = bias[col + 1];
            #pragma unroll
            for (int hm = 0; hm < 2; hm++) {
                int row = rbase + i * 16 + hm * 8;
                float v0 = acc[i][j][hm * 2 + 0] + b0;
                float v1 = acc[i][j][hm * 2 + 1] + b1;
                if (EPI == 1) {
                    const float2 r2 = *reinterpret_cast<const float2*>(
                        R + (size_t)row * N + col);
                    v0 += r2.x; v1 += r2.y;
                    *reinterpret_cast<float2*>((float*)out + (size_t)row * N + col)
                        = make_float2(v0, v1);
                } else {
                    if (EPI == 2) { v0 = gelu(v0); v1 = gelu(v1); }
                    *reinterpret_cast<__half2*>((__half*)out + (size_t)row * N + col)
                        = __floats2half2_rn(v0, v1);
                }
            }
        }
    }
}

// ---------------------------------------------------------------------------
// LayerNorm: one warp per token, fp32 in -> fp16 out
// ---------------------------------------------------------------------------
__global__ __launch_bounds__(256) void ln_kernel(const float* __restrict__ x,
                                                 const float* __restrict__ g,
                                                 const float* __restrict__ b,
                                                 __half* __restrict__ y) {
    int warp = threadIdx.x >> 5, lane = threadIdx.x & 31;
    int m = blockIdx.x * 8 + warp;
    const float4* xr = reinterpret_cast<const float4*>(x + (size_t)m * C_DIM);
    float4 v0 = xr[lane], v1 = xr[lane + 32], v2 = xr[lane + 64];

    float s  = v0.x + v0.y + v0.z + v0.w + v1.x + v1.y + v1.z + v1.w
             + v2.x + v2.y + v2.z + v2.w;
    float sq = v0.x*v0.x + v0.y*v0.y + v0.z*v0.z + v0.w*v0.w
             + v1.x*v1.x + v1.y*v1.y + v1.z*v1.z + v1.w*v1.w
             + v2.x*v2.x + v2.y*v2.y + v2.z*v2.z + v2.w*v2.w;
    #pragma unroll
    for (int o = 16; o; o >>= 1) {
        s  += __shfl_xor_sync(0xffffffffu, s,  o);
        sq += __shfl_xor_sync(0xffffffffu, sq, o);
    }
    float mean = s * (1.0f / 384.0f);
    float var  = sq * (1.0f / 384.0f) - mean * mean;
    float rstd = rsqrtf(var + 1e-5f);

    const float4* gr = reinterpret_cast<const float4*>(g);
    const float4* br = reinterpret_cast<const float4*>(b);
    __half2* yr = reinterpret_cast<__half2*>(y + (size_t)m * C_DIM);
    #pragma unroll
    for (int t = 0; t < 3; t++) {
        int p = lane + 32 * t;
        float4 xv = (t == 0) ? v0 : (t == 1) ? v1 : v2;
        float4 gv = gr[p], bv = br[p];
        yr[p * 2 + 0] = __floats2half2_rn((xv.x - mean) * rstd * gv.x + bv.x,
                                          (xv.y - mean) * rstd * gv.y + bv.y);
        yr[p * 2 + 1] = __floats2half2_rn((xv.z - mean) * rstd * gv.z + bv.z,
                                          (xv.w - mean) * rstd * gv.w + bv.w);
    }
}

// ---------------------------------------------------------------------------
// Windowed shifted attention: one block per (head, window); fp16 I/O;
// float4-vectorized QK and PV loops.
// ---------------------------------------------------------------------------
__global__ __launch_bounds__(256) void attn_kernel(const __half* __restrict__ qkv,
                                                   const float* __restrict__ table,
                                                   const int* __restrict__ relidx,
                                                   __half* __restrict__ o) {
    __shared__ __align__(16) float qs[NWIN][36], ks[NWIN][36], vs[NWIN][36];
    __shared__ float ss[NWIN][52];
    __shared__ int   sidx[NWIN];

    int head = blockIdx.x;
    int w    = blockIdx.y;
    int tid  = threadIdx.x, warp = tid >> 5, lane = tid & 31;

    int b  = w >> 6;
    int wr = w & 63;
    int wi = wr >> 3, wj = wr & 7;

    if (tid < NWIN) {
        int i = tid / 7, j = tid - 7 * (tid / 7);
        int rr = wi * 7 + i + SHIFT; if (rr >= HDIM) rr -= HDIM;
        int cc = wj * 7 + j + SHIFT; if (cc >= HDIM) cc -= HDIM;
        sidx[tid] = b * (HDIM * HDIM) + rr * HDIM + cc;
    }
    __syncthreads();

    for (int r = warp; r < NWIN; r += 8) {
        const __half* base = qkv + (size_t)sidx[r] * (3 * C_DIM) + head * HEADD;
        qs[r][lane] = __half2float(base[lane]);
        ks[r][lane] = __half2float(base[C_DIM + lane]);
        vs[r][lane] = __half2float(base[2 * C_DIM + lane]);
    }
    __syncthreads();

    const float scale = 0.17677669529663687f;
    for (int e = tid; e < NWIN * NWIN; e += 256) {
        int i = e / NWIN, j = e - i * NWIN;
        const float4* q4 = reinterpret_cast<const float4*>(&qs[i][0]);
        const float4* k4 = reinterpret_cast<const float4*>(&ks[j][0]);
        float sx = 0.f, sy = 0.f, sz = 0.f, sw = 0.f;
        #pragma unroll
        for (int t = 0; t < 8; t++) {
            float4 a = q4[t], c = k4[t];
            sx += a.x * c.x; sy += a.y * c.y; sz += a.z * c.z; sw += a.w * c.w;
        }
        ss[i][j] = (sx + sy + sz + sw) * scale + table[relidx[e] * NHEADS + head];
    }
    __syncthreads();

    for (int i = warp; i < NWIN; i += 8) {
        float mx = -1e30f;
        for (int j = lane; j < NWIN; j += 32) mx = fmaxf(mx, ss[i][j]);
        #pragma unroll
        for (int off = 16; off; off >>= 1)
            mx = fmaxf(mx, __shfl_xor_sync(0xffffffffu, mx, off));
        float sum = 0.0f;
        for (int j = lane; j < NWIN; j += 32) {
            float p = __expf(ss[i][j] - mx);
            ss[i][j] = p;
            sum += p;
        }
        #pragma unroll
        for (int off = 16; off; off >>= 1)
            sum += __shfl_xor_sync(0xffffffffu, sum, off);
        float inv = 1.0f / sum;
        for (int j = lane; j < NWIN; j += 32) ss[i][j] *= inv;
    }
    __syncthreads();

    // O = P @ V, float4 over head-dim (8 chunks of 4)
    for (int e = tid; e < NWIN * 8; e += 256) {
        int i = e >> 3, dq = e & 7;
        float ax = 0.f, ay = 0.f, az = 0.f, aw = 0.f;
        #pragma unroll 7
        for (int j = 0; j < NWIN; j++) {
            float p = ss[i][j];
            float4 v = *reinterpret_cast<const float4*>(&vs[j][dq * 4]);
            ax += p * v.x; ay += p * v.y; az += p * v.z; aw += p * v.w;
        }
        __half2 h0 = __floats2half2_rn(ax, ay);
        __half2 h1 = __floats2half2_rn(az, aw);
        uint2 pk = make_uint2(*reinterpret_cast<uint32_t*>(&h0),
                              *reinterpret_cast<uint32_t*>(&h1));
        *reinterpret_cast<uint2*>(o + (size_t)sidx[i] * C_DIM + head * HEADD + dq * 4)
            = pk;
    }
}

// ---------------------------------------------------------------------------
extern "C" void kernel_launch(void* const* d_in, const int* in_sizes, int n_in,
                              void* d_out, int out_size) {
    const float* x      = (const float*)d_in[0];
    const float* n1g    = (const float*)d_in[1];
    const float* n1b    = (const float*)d_in[2];
    const float* qkvw   = (const float*)d_in[3];
    const float* qkvb   = (const float*)d_in[4];
    const float* projw  = (const float*)d_in[5];
    const float* projb  = (const float*)d_in[6];
    const float* table  = (const float*)d_in[7];
    const float* n2g    = (const float*)d_in[8];
    const float* n2b    = (const float*)d_in[9];
    const float* fc1w   = (const float*)d_in[10];
    const float* fc1b   = (const float*)d_in[11];
    const float* fc2w   = (const float*)d_in[12];
    const float* fc2b   = (const float*)d_in[13];
    const int*   relidx = (const int*)d_in[14];
    float* out = (float*)d_out;

    __half *ln, *qkv, *o, *a1, *btq, *btp, *bt1, *bt2;
    float *h;
    cudaGetSymbolAddress((void**)&ln,  g_ln);
    cudaGetSymbolAddress((void**)&qkv, g_qkv);
    cudaGetSymbolAddress((void**)&o,   g_o);
    cudaGetSymbolAddress((void**)&h,   g_h);
    cudaGetSymbolAddress((void**)&a1,  g_a1);
    cudaGetSymbolAddress((void**)&btq, g_bt_qkv);
    cudaGetSymbolAddress((void**)&btp, g_bt_proj);
    cudaGetSymbolAddress((void**)&bt1, g_bt_fc1);
    cudaGetSymbolAddress((void**)&bt2, g_bt_fc2);

    cudaFuncSetAttribute(gemm_hmma<0>, cudaFuncAttributeMaxDynamicSharedMemorySize, SMEM_BYTES);
    cudaFuncSetAttribute(gemm_hmma<1>, cudaFuncAttributeMaxDynamicSharedMemorySize, SMEM_BYTES);
    cudaFuncSetAttribute(gemm_hmma<2>, cudaFuncAttributeMaxDynamicSharedMemorySize, SMEM_BYTES);

    // weight prep (fp32 [K][N] -> fp16 [N][K])
    prep_w<<<(C_DIM * 3 * C_DIM) / 256, 256>>>(qkvw, btq, C_DIM, 3 * C_DIM);
    prep_w<<<(C_DIM * C_DIM) / 256,     256>>>(projw, btp, C_DIM, C_DIM);
    prep_w<<<(C_DIM * MLP_HID) / 256,   256>>>(fc1w, bt1, C_DIM, MLP_HID);
    prep_w<<<(MLP_HID * C_DIM) / 256,   256>>>(fc2w, bt2, MLP_HID, C_DIM);

    // 1) LN1: x -> ln (fp16)
    ln_kernel<<<M_TOK / 8, 256>>>(x, n1g, n1b, ln);
    // 2) qkv = ln @ qkv_w + b   (fp16 out)
    gemm_hmma<0><<<dim3(3 * C_DIM / 128, M_TOK / 128), 256, SMEM_BYTES>>>(
        ln, btq, qkvb, nullptr, qkv, M_TOK, 3 * C_DIM, C_DIM);
    // 3) windowed attention (shift folded into indices), fp16 out
    attn_kernel<<<dim3(NHEADS, 2048), 256>>>(qkv, table, relidx, o);
    // 4) h = x + proj(o)   (fp32 out)
    gemm_hmma<1><<<dim3(C_DIM / 128, M_TOK / 128), 256, SMEM_BYTES>>>(
        o, btp, projb, x, h, M_TOK, C_DIM, C_DIM);
    // 5) LN2: h -> ln (fp16)
    ln_kernel<<<M_TOK / 8, 256>>>(h, n2g, n2b, ln);
    // 6) a1 = gelu(fc1(ln))  (fp16 out)
    gemm_hmma<2><<<dim3(MLP_HID / 128, M_TOK / 128), 256, SMEM_BYTES>>>(
        ln, bt1, fc1b, nullptr, a1, M_TOK, MLP_HID, C_DIM);
    // 7) out = h + fc2(a1)   (fp32 out)
    gemm_hmma<1><<<dim3(C_DIM / 128, M_TOK / 128), 256, SMEM_BYTES>>>(
        a1, bt2, fc2b, h, out, M_TOK, C_DIM, MLP_HID);
}

// round 5
// speedup vs baseline: 4.3519x; 1.0081x over previous
#include <cuda_runtime.h>
#include <cuda_fp16.h>
#include <math.h>
#include <stdint.h>

// Problem constants
constexpr int BATCH   = 32;
constexpr int HDIM    = 56;
constexpr int C_DIM   = 384;
constexpr int NHEADS  = 12;
constexpr int HEADD   = 32;
constexpr int WS      = 7;
constexpr int SHIFT   = 3;
constexpr int NWIN    = 49;
constexpr int M_TOK   = BATCH * HDIM * HDIM;   // 100352
constexpr int MLP_HID = 4 * C_DIM;             // 1536

constexpr int NSTAGE     = 3;
constexpr int STAGE_B    = 32768;              // A 16KB + B 16KB (fp16, k64)
constexpr int SMEM_BYTES = NSTAGE * STAGE_B;   // 96KB per CTA

// Scratch buffers (device globals: no allocation allowed)
__device__ __align__(256) __half g_ln [(size_t)M_TOK * C_DIM];
__device__ __align__(256) __half g_qkv[(size_t)M_TOK * 3 * C_DIM];
__device__ __align__(256) __half g_o  [(size_t)M_TOK * C_DIM];
__device__ __align__(256) float  g_h  [(size_t)M_TOK * C_DIM];
__device__ __align__(256) __half g_a1 [(size_t)M_TOK * MLP_HID];
// fp16 transposed weights [N][K]
__device__ __align__(256) __half g_bt_qkv [(size_t)3 * C_DIM * C_DIM];
__device__ __align__(256) __half g_bt_proj[(size_t)C_DIM * C_DIM];
__device__ __align__(256) __half g_bt_fc1 [(size_t)MLP_HID * C_DIM];
__device__ __align__(256) __half g_bt_fc2 [(size_t)C_DIM * MLP_HID];

// ---------------------------------------------------------------------------
// asm helpers (base-arch only: cp.async sm80, ldmatrix sm75, mma.sync sm80)
// ---------------------------------------------------------------------------
__device__ __forceinline__ uint32_t smem_u32(const void* p) {
    uint32_t a;
    asm("{ .reg .u64 t; cvta.to.shared.u64 t, %1; cvt.u32.u64 %0, t; }"
        : "=r"(a) : "l"(p));
    return a;
}
__device__ __forceinline__ void cp16(uint32_t dst, const void* src) {
    asm volatile("cp.async.cg.shared.global [%0], [%1], 16;"
                 :: "r"(dst), "l"(src) : "memory");
}
__device__ __forceinline__ void cp_commit() {
    asm volatile("cp.async.commit_group;" ::: "memory");
}
template <int N>
__device__ __forceinline__ void cp_wait() {
    asm volatile("cp.async.wait_group %0;" :: "n"(N) : "memory");
}
__device__ __forceinline__ void ldmx4(uint32_t& r0, uint32_t& r1,
                                      uint32_t& r2, uint32_t& r3, uint32_t addr) {
    asm volatile("ldmatrix.sync.aligned.m8n8.x4.shared.b16 {%0,%1,%2,%3}, [%4];"
                 : "=r"(r0), "=r"(r1), "=r"(r2), "=r"(r3) : "r"(addr));
}
__device__ __forceinline__ void mma16816(float* c, const uint32_t* a,
                                         const uint32_t* b) {
    asm volatile(
        "mma.sync.aligned.m16n8k16.row.col.f32.f16.f16.f32 "
        "{%0,%1,%2,%3}, {%4,%5,%6,%7}, {%8,%9}, {%0,%1,%2,%3};"
        : "+f"(c[0]), "+f"(c[1]), "+f"(c[2]), "+f"(c[3])
        : "r"(a[0]), "r"(a[1]), "r"(a[2]), "r"(a[3]), "r"(b[0]), "r"(b[1]));
}
// smem tile: [128 rows][64 fp16] = 128B rows (8x16B chunks), XOR-8 swizzle
__device__ __forceinline__ uint32_t sa_off(int row, int c4) {
    return (uint32_t)(row * 128 + ((c4 ^ (row & 7)) << 4));
}
__device__ __forceinline__ float gelu(float v) {
    return 0.5f * v * (1.0f + erff(v * 0.70710678118654752f));
}

// ---------------------------------------------------------------------------
// Weight prep: W[K][N] fp32 -> Wt[N][K] fp16
// ---------------------------------------------------------------------------
__global__ __launch_bounds__(256) void prep_w(const float* __restrict__ W,
                                              __half* __restrict__ Wt,
                                              int K, int N) {
    int idx = blockIdx.x * 256 + threadIdx.x;
    if (idx >= K * N) return;
    int k = idx / N, n = idx - k * N;
    Wt[(size_t)n * K + k] = __float2half_rn(W[idx]);
}

// ---------------------------------------------------------------------------
// fp16 HMMA GEMM: C[M,N] = A[M,K] @ Bt[N,K]^T  (+bias / +res / gelu)
// 128x128 CTA tile, 128 thr, 4 warps (2x2 -> 64x64 warp tile),
// K-chunk 64, 3-stage cp.async pipeline, 2 CTAs/SM.
// EPI: 0 = +bias -> half ; 1 = +bias+res -> float ; 2 = gelu(+bias) -> half
// ---------------------------------------------------------------------------
template <int EPI>
__global__ __launch_bounds__(128, 2)
void gemm_hmma(const __half* __restrict__ A, const __half* __restrict__ Bt,
               const float* __restrict__ bias, const float* __restrict__ R,
               void* __restrict__ out, int M, int N, int K) {
    extern __shared__ __align__(128) char smem[];
    uint32_t sbase = smem_u32(smem);

    int tid = threadIdx.x, warp = tid >> 5, lane = tid & 31;
    int wm = warp >> 1, wn = warp & 1;
    int m0 = blockIdx.y * 128, n0 = blockIdx.x * 128;
    int NC = K >> 6;   // k64 chunks

    float acc[4][8][4];
    #pragma unroll
    for (int i = 0; i < 4; i++)
        #pragma unroll
        for (int j = 0; j < 8; j++)
            #pragma unroll
            for (int e = 0; e < 4; e++) acc[i][j][e] = 0.0f;

    auto load_chunk = [&](int kc, int s) {
        uint32_t ast = sbase + s * STAGE_B;
        uint32_t bst = ast + 16384;
        #pragma unroll
        for (int t = 0; t < 8; t++) {
            int seg = tid + t * 128;
            int row = seg >> 3, q = seg & 7;          // 8 chunks per 128B row
            cp16(ast + sa_off(row, q),
                 A + (size_t)(m0 + row) * K + kc * 64 + q * 8);
            cp16(bst + sa_off(row, q),
                 Bt + (size_t)(n0 + row) * K + kc * 64 + q * 8);
        }
    };

    // prologue: 2 stages in flight
    #pragma unroll
    for (int c = 0; c < NSTAGE - 1; c++) { load_chunk(c, c); cp_commit(); }

    int s_cur = 0, s_nxt = NSTAGE - 1;
    for (int c = 0; c < NC; c++) {
        cp_wait<NSTAGE - 2>();
        __syncthreads();
        int cn = c + NSTAGE - 1;
        if (cn < NC) load_chunk(cn, s_nxt);
        cp_commit();
        if (++s_nxt == NSTAGE) s_nxt = 0;

        uint32_t ast = sbase + s_cur * STAGE_B;
        uint32_t bst = ast + 16384;
        if (++s_cur == NSTAGE) s_cur = 0;

        #pragma unroll
        for (int kk = 0; kk < 4; kk++) {
            uint32_t a[4][4], b[4][4];
            #pragma unroll
            for (int i = 0; i < 4; i++) {
                int row = wm * 64 + i * 16 + (lane & 15);
                int c4  = kk * 2 + (lane >> 4);
                ldmx4(a[i][0], a[i][1], a[i][2], a[i][3], ast + sa_off(row, c4));
            }
            #pragma unroll
            for (int jp = 0; jp < 4; jp++) {
                int row = wn * 64 + jp * 16 + (lane & 7) + ((lane >> 4) << 3);
                int c4  = kk * 2 + ((lane >> 3) & 1);
                ldmx4(b[jp][0], b[jp][1], b[jp][2], b[jp][3], bst + sa_off(row, c4));
            }
            #pragma unroll
            for (int i = 0; i < 4; i++)
                #pragma unroll
                for (int jp = 0; jp < 4; jp++) {
                    mma16816(acc[i][jp * 2 + 0], a[i], &b[jp][0]);
                    mma16816(acc[i][jp * 2 + 1], a[i], &b[jp][2]);
                }
        }
    }

    // register epilogue
    int rbase = m0 + wm * 64 + (lane >> 2);
    #pragma unroll
    for (int i = 0; i < 4; i++) {
        #pragma unroll
        for (int j = 0; j < 8; j++) {
            int col = n0 + wn * 64 + j * 8 + ((lane & 3) << 1);
            float b0 = bias[col], b1 = bias[col + 1];
            #pragma unroll
            for (int hm = 0; hm < 2; hm++) {
                int row = rbase + i * 16 + hm * 8;
                float v0 = acc[i][j][hm * 2 + 0] + b0;
                float v1 = acc[i][j][hm * 2 + 1] + b1;
                if (EPI == 1) {
                    const float2 r2 = *reinterpret_cast<const float2*>(
                        R + (size_t)row * N + col);
                    v0 += r2.x; v1 += r2.y;
                    *reinterpret_cast<float2*>((float*)out + (size_t)row * N + col)
                        = make_float2(v0, v1);
                } else {
                    if (EPI == 2) { v0 = gelu(v0); v1 = gelu(v1); }
                    *reinterpret_cast<__half2*>((__half*)out + (size_t)row * N + col)
                        = __floats2half2_rn(v0, v1);
                }
            }
        }
    }
}

// ---------------------------------------------------------------------------
// LayerNorm: one warp per token, fp32 in -> fp16 out
// ---------------------------------------------------------------------------
__global__ __launch_bounds__(256) void ln_kernel(const float* __restrict__ x,
                                                 const float* __restrict__ g,
                                                 const float* __restrict__ b,
                                                 __half* __restrict__ y) {
    int warp = threadIdx.x >> 5, lane = threadIdx.x & 31;
    int m = blockIdx.x * 8 + warp;
    const float4* xr = reinterpret_cast<const float4*>(x + (size_t)m * C_DIM);
    float4 v0 = xr[lane], v1 = xr[lane + 32], v2 = xr[lane + 64];

    float s  = v0.x + v0.y + v0.z + v0.w + v1.x + v1.y + v1.z + v1.w
             + v2.x + v2.y + v2.z + v2.w;
    float sq = v0.x*v0.x + v0.y*v0.y + v0.z*v0.z + v0.w*v0.w
             + v1.x*v1.x + v1.y*v1.y + v1.z*v1.z + v1.w*v1.w
             + v2.x*v2.x + v2.y*v2.y + v2.z*v2.z + v2.w*v2.w;
    #pragma unroll
    for (int o = 16; o; o >>= 1) {
        s  += __shfl_xor_sync(0xffffffffu, s,  o);
        sq += __shfl_xor_sync(0xffffffffu, sq, o);
    }
    float mean = s * (1.0f / 384.0f);
    float var  = sq * (1.0f / 384.0f) - mean * mean;
    float rstd = rsqrtf(var + 1e-5f);

    const float4* gr = reinterpret_cast<const float4*>(g);
    const float4* br = reinterpret_cast<const float4*>(b);
    __half2* yr = reinterpret_cast<__half2*>(y + (size_t)m * C_DIM);
    #pragma unroll
    for (int t = 0; t < 3; t++) {
        int p = lane + 32 * t;
        float4 xv = (t == 0) ? v0 : (t == 1) ? v1 : v2;
        float4 gv = gr[p], bv = br[p];
        yr[p * 2 + 0] = __floats2half2_rn((xv.x - mean) * rstd * gv.x + bv.x,
                                          (xv.y - mean) * rstd * gv.y + bv.y);
        yr[p * 2 + 1] = __floats2half2_rn((xv.z - mean) * rstd * gv.z + bv.z,
                                          (xv.w - mean) * rstd * gv.w + bv.w);
    }
}

// ---------------------------------------------------------------------------
// Windowed shifted attention: one block per (head, window); fp16 I/O;
// float4-vectorized QK and PV loops.
// ---------------------------------------------------------------------------
__global__ __launch_bounds__(256) void attn_kernel(const __half* __restrict__ qkv,
                                                   const float* __restrict__ table,
                                                   const int* __restrict__ relidx,
                                                   __half* __restrict__ o) {
    __shared__ __align__(16) float qs[NWIN][36], ks[NWIN][36], vs[NWIN][36];
    __shared__ float ss[NWIN][52];
    __shared__ int   sidx[NWIN];

    int head = blockIdx.x;
    int w    = blockIdx.y;
    int tid  = threadIdx.x, warp = tid >> 5, lane = tid & 31;

    int b  = w >> 6;
    int wr = w & 63;
    int wi = wr >> 3, wj = wr & 7;

    if (tid < NWIN) {
        int i = tid / 7, j = tid - 7 * (tid / 7);
        int rr = wi * 7 + i + SHIFT; if (rr >= HDIM) rr -= HDIM;
        int cc = wj * 7 + j + SHIFT; if (cc >= HDIM) cc -= HDIM;
        sidx[tid] = b * (HDIM * HDIM) + rr * HDIM + cc;
    }
    __syncthreads();

    for (int r = warp; r < NWIN; r += 8) {
        const __half* base = qkv + (size_t)sidx[r] * (3 * C_DIM) + head * HEADD;
        qs[r][lane] = __half2float(base[lane]);
        ks[r][lane] = __half2float(base[C_DIM + lane]);
        vs[r][lane] = __half2float(base[2 * C_DIM + lane]);
    }
    __syncthreads();

    const float scale = 0.17677669529663687f;
    for (int e = tid; e < NWIN * NWIN; e += 256) {
        int i = e / NWIN, j = e - i * NWIN;
        const float4* q4 = reinterpret_cast<const float4*>(&qs[i][0]);
        const float4* k4 = reinterpret_cast<const float4*>(&ks[j][0]);
        float sx = 0.f, sy = 0.f, sz = 0.f, sw = 0.f;
        #pragma unroll
        for (int t = 0; t < 8; t++) {
            float4 a = q4[t], c = k4[t];
            sx += a.x * c.x; sy += a.y * c.y; sz += a.z * c.z; sw += a.w * c.w;
        }
        ss[i][j] = (sx + sy + sz + sw) * scale + table[relidx[e] * NHEADS + head];
    }
    __syncthreads();

    for (int i = warp; i < NWIN; i += 8) {
        float mx = -1e30f;
        for (int j = lane; j < NWIN; j += 32) mx = fmaxf(mx, ss[i][j]);
        #pragma unroll
        for (int off = 16; off; off >>= 1)
            mx = fmaxf(mx, __shfl_xor_sync(0xffffffffu, mx, off));
        float sum = 0.0f;
        for (int j = lane; j < NWIN; j += 32) {
            float p = __expf(ss[i][j] - mx);
            ss[i][j] = p;
            sum += p;
        }
        #pragma unroll
        for (int off = 16; off; off >>= 1)
            sum += __shfl_xor_sync(0xffffffffu, sum, off);
        float inv = 1.0f / sum;
        for (int j = lane; j < NWIN; j += 32) ss[i][j] *= inv;
    }
    __syncthreads();

    // O = P @ V, float4 over head-dim (8 chunks of 4)
    for (int e = tid; e < NWIN * 8; e += 256) {
        int i = e >> 3, dq = e & 7;
        float ax = 0.f, ay = 0.f, az = 0.f, aw = 0.f;
        #pragma unroll 7
        for (int j = 0; j < NWIN; j++) {
            float p = ss[i][j];
            float4 v = *reinterpret_cast<const float4*>(&vs[j][dq * 4]);
            ax += p * v.x; ay += p * v.y; az += p * v.z; aw += p * v.w;
        }
        __half2 h0 = __floats2half2_rn(ax, ay);
        __half2 h1 = __floats2half2_rn(az, aw);
        uint2 pk = make_uint2(*reinterpret_cast<uint32_t*>(&h0),
                              *reinterpret_cast<uint32_t*>(&h1));
        *reinterpret_cast<uint2*>(o + (size_t)sidx[i] * C_DIM + head * HEADD + dq * 4)
            = pk;
    }
}

// ---------------------------------------------------------------------------
extern "C" void kernel_launch(void* const* d_in, const int* in_sizes, int n_in,
                              void* d_out, int out_size) {
    const float* x      = (const float*)d_in[0];
    const float* n1g    = (const float*)d_in[1];
    const float* n1b    = (const float*)d_in[2];
    const float* qkvw   = (const float*)d_in[3];
    const float* qkvb   = (const float*)d_in[4];
    const float* projw  = (const float*)d_in[5];
    const float* projb  = (const float*)d_in[6];
    const float* table  = (const float*)d_in[7];
    const float* n2g    = (const float*)d_in[8];
    const float* n2b    = (const float*)d_in[9];
    const float* fc1w   = (const float*)d_in[10];
    const float* fc1b   = (const float*)d_in[11];
    const float* fc2w   = (const float*)d_in[12];
    const float* fc2b   = (const float*)d_in[13];
    const int*   relidx = (const int*)d_in[14];
    float* out = (float*)d_out;

    __half *ln, *qkv, *o, *a1, *btq, *btp, *bt1, *bt2;
    float *h;
    cudaGetSymbolAddress((void**)&ln,  g_ln);
    cudaGetSymbolAddress((void**)&qkv, g_qkv);
    cudaGetSymbolAddress((void**)&o,   g_o);
    cudaGetSymbolAddress((void**)&h,   g_h);
    cudaGetSymbolAddress((void**)&a1,  g_a1);
    cudaGetSymbolAddress((void**)&btq, g_bt_qkv);
    cudaGetSymbolAddress((void**)&btp, g_bt_proj);
    cudaGetSymbolAddress((void**)&bt1, g_bt_fc1);
    cudaGetSymbolAddress((void**)&bt2, g_bt_fc2);

    cudaFuncSetAttribute(gemm_hmma<0>, cudaFuncAttributeMaxDynamicSharedMemorySize, SMEM_BYTES);
    cudaFuncSetAttribute(gemm_hmma<1>, cudaFuncAttributeMaxDynamicSharedMemorySize, SMEM_BYTES);
    cudaFuncSetAttribute(gemm_hmma<2>, cudaFuncAttributeMaxDynamicSharedMemorySize, SMEM_BYTES);

    // weight prep (fp32 [K][N] -> fp16 [N][K])
    prep_w<<<(C_DIM * 3 * C_DIM) / 256, 256>>>(qkvw, btq, C_DIM, 3 * C_DIM);
    prep_w<<<(C_DIM * C_DIM) / 256,     256>>>(projw, btp, C_DIM, C_DIM);
    prep_w<<<(C_DIM * MLP_HID) / 256,   256>>>(fc1w, bt1, C_DIM, MLP_HID);
    prep_w<<<(MLP_HID * C_DIM) / 256,   256>>>(fc2w, bt2, MLP_HID, C_DIM);

    // 1) LN1: x -> ln (fp16)
    ln_kernel<<<M_TOK / 8, 256>>>(x, n1g, n1b, ln);
    // 2) qkv = ln @ qkv_w + b   (fp16 out)
    gemm_hmma<0><<<dim3(3 * C_DIM / 128, M_TOK / 128), 128, SMEM_BYTES>>>(
        ln, btq, qkvb, nullptr, qkv, M_TOK, 3 * C_DIM, C_DIM);
    // 3) windowed attention (shift folded into indices), fp16 out
    attn_kernel<<<dim3(NHEADS, 2048), 256>>>(qkv, table, relidx, o);
    // 4) h = x + proj(o)   (fp32 out)
    gemm_hmma<1><<<dim3(C_DIM / 128, M_TOK / 128), 128, SMEM_BYTES>>>(
        o, btp, projb, x, h, M_TOK, C_DIM, C_DIM);
    // 5) LN2: h -> ln (fp16)
    ln_kernel<<<M_TOK / 8, 256>>>(h, n2g, n2b, ln);
    // 6) a1 = gelu(fc1(ln))  (fp16 out)
    gemm_hmma<2><<<dim3(MLP_HID / 128, M_TOK / 128), 128, SMEM_BYTES>>>(
        ln, bt1, fc1b, nullptr, a1, M_TOK, MLP_HID, C_DIM);
    // 7) out = h + fc2(a1)   (fp32 out)
    gemm_hmma<1><<<dim3(C_DIM / 128, M_TOK / 128), 128, SMEM_BYTES>>>(
        a1, bt2, fc2b, h, out, M_TOK, C_DIM, MLP_HID);
}